// round 1
// baseline (speedup 1.0000x reference)
#include <cuda_runtime.h>

#define RES 300
#define NCH 64            // NC_A + NC_D
#define NC_A 48
#define APP_DIM 27

// Scratch: transposed tables (device globals are allowed; no runtime alloc)
__device__ float g_plane_t[3 * RES * RES * NCH];   // (i, h, w, c)  c contiguous
__device__ float g_line_t[3 * RES * NCH];          // (i, h, c)     c contiguous

// ---------------------------------------------------------------------------
// Transpose plane_coef (3, 64, 300, 300) -> (3, 300, 300, 64)
// block handles one (i, h) row and a 30-wide w-chunk; smem tile for coalescing
// ---------------------------------------------------------------------------
__global__ void transpose_plane_kernel(const float* __restrict__ in) {
    int ih = blockIdx.x;            // 0..899
    int i = ih / RES, h = ih % RES;
    int w0 = blockIdx.y * 30;       // 10 chunks of 30 -> 300

    __shared__ float tile[NCH][31]; // +1 pad to break bank conflicts

    for (int idx = threadIdx.x; idx < NCH * 30; idx += blockDim.x) {
        int c = idx / 30, w = idx % 30;
        tile[c][w] = in[(((size_t)i * NCH + c) * RES + h) * RES + w0 + w];
    }
    __syncthreads();
    float* dst = g_plane_t + (((size_t)i * RES + h) * RES + w0) * NCH;
    for (int idx = threadIdx.x; idx < NCH * 30; idx += blockDim.x) {
        int w = idx / NCH, c = idx % NCH;
        dst[(size_t)w * NCH + c] = tile[c][w];
    }
}

// Transpose line_coef (3, 64, 300, 1) -> (3, 300, 64). Tiny (230 KB).
__global__ void transpose_line_kernel(const float* __restrict__ in) {
    int ih = blockIdx.x;            // 0..899
    int i = ih / RES, h = ih % RES;
    int c = threadIdx.x;            // 64 threads
    g_line_t[((size_t)i * RES + h) * NCH + c] =
        in[((size_t)i * NCH + c) * RES + h];
}

// ---------------------------------------------------------------------------
// Fused: bilinear plane gather * line interp -> sigma + basis projection
// One thread per sample.
// ---------------------------------------------------------------------------
__global__ void __launch_bounds__(128)
fused_kernel(const float* __restrict__ xyz,
             const float* __restrict__ basisW,   // (27, 144) row-major
             float* __restrict__ out, int N)
{
    // Wsm[j][d] = basisW[d][j], row padded to 28 floats (112B, 16B aligned)
    __shared__ __align__(16) float Wsm[3 * NC_A][APP_DIM + 1];

    for (int idx = threadIdx.x; idx < 3 * NC_A; idx += blockDim.x)
        Wsm[idx][APP_DIM] = 0.f;                     // zero the pad column
    for (int idx = threadIdx.x; idx < APP_DIM * 3 * NC_A; idx += blockDim.x) {
        int d = idx / (3 * NC_A), j = idx % (3 * NC_A);
        Wsm[j][d] = basisW[idx];                     // coalesced read
    }
    __syncthreads();

    int n = blockIdx.x * blockDim.x + threadIdx.x;
    if (n >= N) return;

    float coords[3];
    coords[0] = xyz[3 * n + 0];
    coords[1] = xyz[3 * n + 1];
    coords[2] = xyz[3 * n + 2];

    float acc[APP_DIM + 1];
#pragma unroll
    for (int d = 0; d < APP_DIM + 1; d++) acc[d] = 0.f;
    float sigma = 0.f;

    const int M0[3] = {0, 0, 1};   // x (W) coord source per mode
    const int M1[3] = {1, 2, 2};   // y (H) coord source per mode
    const int VM[3] = {2, 1, 0};   // line coord source per mode

#pragma unroll
    for (int i = 0; i < 3; i++) {
        float gx = coords[M0[i]];
        float gy = coords[M1[i]];
        float gz = coords[VM[i]];

        float ix = (gx + 1.f) * 0.5f * (float)(RES - 1);
        float iy = (gy + 1.f) * 0.5f * (float)(RES - 1);
        float iz = (gz + 1.f) * 0.5f * (float)(RES - 1);
        float x0f = floorf(ix), y0f = floorf(iy), z0f = floorf(iz);
        int x0 = (int)x0f, y0 = (int)y0f, z0 = (int)z0f;
        float wx = ix - x0f, wy = iy - y0f, wz = iz - z0f;
        int x1 = x0 + 1, y1 = y0 + 1, z1 = z0 + 1;
        // zeros-padding: upper edge corner gets weight 0 (coords in [-1,1])
        if (x1 > RES - 1) { x1 = RES - 1; wx = 0.f; }
        if (y1 > RES - 1) { y1 = RES - 1; wy = 0.f; }
        if (z1 > RES - 1) { z1 = RES - 1; wz = 0.f; }

        float w00 = (1.f - wx) * (1.f - wy);
        float w01 = wx * (1.f - wy);
        float w10 = (1.f - wx) * wy;
        float w11 = wx * wy;
        float wl0 = 1.f - wz, wl1 = wz;

        const float4* P00 = (const float4*)(g_plane_t + (((size_t)i * RES + y0) * RES + x0) * NCH);
        const float4* P01 = (const float4*)(g_plane_t + (((size_t)i * RES + y0) * RES + x1) * NCH);
        const float4* P10 = (const float4*)(g_plane_t + (((size_t)i * RES + y1) * RES + x0) * NCH);
        const float4* P11 = (const float4*)(g_plane_t + (((size_t)i * RES + y1) * RES + x1) * NCH);
        const float4* L0  = (const float4*)(g_line_t  + ((size_t)i * RES + z0) * NCH);
        const float4* L1  = (const float4*)(g_line_t  + ((size_t)i * RES + z1) * NCH);

        // ---- app channels: c = 0..47 (c4 = 0..11) ----
#pragma unroll 2
        for (int c4 = 0; c4 < NC_A / 4; c4++) {
            float4 a  = P00[c4], b  = P01[c4], c2 = P10[c4], d2 = P11[c4];
            float4 l0 = L0[c4],  l1 = L1[c4];
            float fx = (w00*a.x + w01*b.x + w10*c2.x + w11*d2.x) * (wl0*l0.x + wl1*l1.x);
            float fy = (w00*a.y + w01*b.y + w10*c2.y + w11*d2.y) * (wl0*l0.y + wl1*l1.y);
            float fz = (w00*a.z + w01*b.z + w10*c2.z + w11*d2.z) * (wl0*l0.z + wl1*l1.z);
            float fw = (w00*a.w + w01*b.w + w10*c2.w + w11*d2.w) * (wl0*l0.w + wl1*l1.w);

            const float* r0 = &Wsm[i * NC_A + c4 * 4 + 0][0];
            const float* r1 = r0 + (APP_DIM + 1);
            const float* r2 = r0 + 2 * (APP_DIM + 1);
            const float* r3 = r0 + 3 * (APP_DIM + 1);
#pragma unroll
            for (int d4 = 0; d4 < 7; d4++) {
                float4 q0 = *(const float4*)(r0 + d4 * 4);
                float4 q1 = *(const float4*)(r1 + d4 * 4);
                float4 q2 = *(const float4*)(r2 + d4 * 4);
                float4 q3 = *(const float4*)(r3 + d4 * 4);
                acc[d4*4+0] += fx*q0.x + fy*q1.x + fz*q2.x + fw*q3.x;
                acc[d4*4+1] += fx*q0.y + fy*q1.y + fz*q2.y + fw*q3.y;
                acc[d4*4+2] += fx*q0.z + fy*q1.z + fz*q2.z + fw*q3.z;
                acc[d4*4+3] += fx*q0.w + fy*q1.w + fz*q2.w + fw*q3.w;
            }
        }

        // ---- density channels: c = 48..63 (c4 = 12..15) ----
#pragma unroll
        for (int c4 = NC_A / 4; c4 < NCH / 4; c4++) {
            float4 a  = P00[c4], b  = P01[c4], c2 = P10[c4], d2 = P11[c4];
            float4 l0 = L0[c4],  l1 = L1[c4];
            float fx = (w00*a.x + w01*b.x + w10*c2.x + w11*d2.x) * (wl0*l0.x + wl1*l1.x);
            float fy = (w00*a.y + w01*b.y + w10*c2.y + w11*d2.y) * (wl0*l0.y + wl1*l1.y);
            float fz = (w00*a.z + w01*b.z + w10*c2.z + w11*d2.z) * (wl0*l0.z + wl1*l1.z);
            float fw = (w00*a.w + w01*b.w + w10*c2.w + w11*d2.w) * (wl0*l0.w + wl1*l1.w);
            sigma += fx + fy + fz + fw;
        }
    }

    // output: [0..N) sigma, then (N, 27) app features row-major
    out[n] = sigma;
    float* ao = out + N + (size_t)n * APP_DIM;
#pragma unroll
    for (int d = 0; d < APP_DIM; d++) ao[d] = acc[d];
}

extern "C" void kernel_launch(void* const* d_in, const int* in_sizes, int n_in,
                              void* d_out, int out_size) {
    const float* xyz   = (const float*)d_in[0];   // (N, 3)
    const float* plane = (const float*)d_in[1];   // (3, 64, 300, 300)
    const float* line  = (const float*)d_in[2];   // (3, 64, 300, 1)
    const float* W     = (const float*)d_in[3];   // (27, 144)
    float* out = (float*)d_out;
    int N = in_sizes[0] / 3;

    transpose_plane_kernel<<<dim3(3 * RES, 10), 256>>>(plane);
    transpose_line_kernel<<<3 * RES, NCH>>>(line);
    fused_kernel<<<(N + 127) / 128, 128>>>(xyz, W, out, N);
}

// round 2
// speedup vs baseline: 1.2707x; 1.2707x over previous
#include <cuda_runtime.h>

#define RES 300
#define NCH 64            // NC_A + NC_D
#define NC_A 48
#define APP_DIM 27
#define SPB 120           // samples per block

// Scratch: transposed tables (device globals allowed; no runtime alloc)
__device__ float g_plane_t[3 * RES * RES * NCH];   // (i, h, w, c)  c contiguous
__device__ float g_line_t[3 * RES * NCH];          // (i, h, c)     c contiguous

// ---------------------------------------------------------------------------
// Transpose plane_coef (3, 64, 300, 300) -> (3, 300, 300, 64)
// ---------------------------------------------------------------------------
__global__ void transpose_plane_kernel(const float* __restrict__ in) {
    int ih = blockIdx.x;            // 0..899
    int i = ih / RES, h = ih % RES;
    int w0 = blockIdx.y * 30;       // 10 chunks of 30 -> 300

    __shared__ float tile[NCH][31];

    for (int idx = threadIdx.x; idx < NCH * 30; idx += blockDim.x) {
        int c = idx / 30, w = idx % 30;
        tile[c][w] = in[(((size_t)i * NCH + c) * RES + h) * RES + w0 + w];
    }
    __syncthreads();
    float* dst = g_plane_t + (((size_t)i * RES + h) * RES + w0) * NCH;
    for (int idx = threadIdx.x; idx < NCH * 30; idx += blockDim.x) {
        int w = idx / NCH, c = idx % NCH;
        dst[(size_t)w * NCH + c] = tile[c][w];
    }
}

__global__ void transpose_line_kernel(const float* __restrict__ in) {
    int ih = blockIdx.x;            // 0..899
    int i = ih / RES, h = ih % RES;
    int c = threadIdx.x;            // 64 threads
    g_line_t[((size_t)i * RES + h) * NCH + c] =
        in[((size_t)i * NCH + c) * RES + h];
}

// ---------------------------------------------------------------------------
// Fused kernel, block-cooperative:
//   phase 1: 16-lane groups gather+blend one (sample,mode), coalesced 256B rows
//   phase 2: one thread per sample: 144x28 projection from smem
// Dynamic smem layout (floats):
//   [0, 360)              xyz for SPB samples
//   [360, 360+4032)       Wsm[144][28]  (transposed basis, zero pad col)
//   [4392, 4392+23520)    Fsm[SPB][196] (192 features + 4 pad; 196 % 32 == 4)
// ---------------------------------------------------------------------------
#define XYZ_OFF 0
#define W_OFF   (3 * SPB)                       // 360
#define F_OFF   (W_OFF + 144 * 28)              // 4392
#define SMEM_FLOATS (F_OFF + SPB * 196)         // 27912 -> 111648 bytes
#define F_ROW4  49                              // 196/4 float4 per row

__global__ void __launch_bounds__(128, 2)
fused_kernel(const float* __restrict__ xyz,
             const float* __restrict__ basisW,   // (27, 144) row-major
             float* __restrict__ out, int N)
{
    extern __shared__ __align__(16) float sm[];
    float*  xyzsm = sm + XYZ_OFF;
    float*  Wsm   = sm + W_OFF;
    float4* F4    = (float4*)(sm + F_OFF);

    const int tid = threadIdx.x;
    const long base = (long)blockIdx.x * SPB;

    // ---- phase 0: stage xyz + W ----
    for (int idx = tid; idx < 3 * SPB; idx += 128) {
        long g = base * 3 + idx;
        xyzsm[idx] = (g < (long)3 * N) ? xyz[g] : 0.f;
    }
    for (int idx = tid; idx < APP_DIM * 144; idx += 128) {
        int d = idx / 144, j = idx - d * 144;
        Wsm[j * 28 + d] = basisW[idx];
    }
    if (tid < 144) Wsm[tid * 28 + 27] = 0.f;
    __syncthreads();

    // ---- phase 1: cooperative gather/blend ----
    const float4* GP = (const float4*)g_plane_t;
    const float4* GL = (const float4*)g_line_t;
    const int l16 = tid & 15;

#pragma unroll 2
    for (int u = (tid >> 4); u < 3 * SPB; u += 8) {
        int s = u / 3;
        int i = u - s * 3;

        float cx = xyzsm[s * 3 + 0];
        float cy = xyzsm[s * 3 + 1];
        float cz = xyzsm[s * 3 + 2];
        // MAT_MODE = {0,1},{0,2},{1,2}; VEC_MODE = {2,1,0}
        float gx = (i == 2) ? cy : cx;                       // x -> W
        float gy = (i == 0) ? cy : cz;                       // y -> H
        float gz = (i == 0) ? cz : ((i == 1) ? cy : cx);     // line coord

        float ix = (gx + 1.f) * 0.5f * (float)(RES - 1);
        float iy = (gy + 1.f) * 0.5f * (float)(RES - 1);
        float iz = (gz + 1.f) * 0.5f * (float)(RES - 1);
        float x0f = floorf(ix), y0f = floorf(iy), z0f = floorf(iz);
        int x0 = (int)x0f, y0 = (int)y0f, z0 = (int)z0f;
        float wx = ix - x0f, wy = iy - y0f, wz = iz - z0f;
        int dx = 1, dy = 1, dz = 1;
        if (x0 + 1 > RES - 1) { dx = 0; wx = 0.f; }
        if (y0 + 1 > RES - 1) { dy = 0; wy = 0.f; }
        if (z0 + 1 > RES - 1) { dz = 0; wz = 0.f; }

        int pbase = ((i * RES + y0) * RES + x0) * (NCH / 4) + l16;
        int lbase = (i * RES + z0) * (NCH / 4) + l16;

        float4 a  = GP[pbase];
        float4 b  = GP[pbase + dx * 16];
        float4 c2 = GP[pbase + dy * (RES * 16)];
        float4 d2 = GP[pbase + dy * (RES * 16) + dx * 16];
        float4 l0 = GL[lbase];
        float4 l1 = GL[lbase + dz * 16];

        float w00 = (1.f - wx) * (1.f - wy);
        float w01 = wx * (1.f - wy);
        float w10 = (1.f - wx) * wy;
        float w11 = wx * wy;
        float wl0 = 1.f - wz, wl1 = wz;

        float4 f;
        f.x = (w00*a.x + w01*b.x + w10*c2.x + w11*d2.x) * (wl0*l0.x + wl1*l1.x);
        f.y = (w00*a.y + w01*b.y + w10*c2.y + w11*d2.y) * (wl0*l0.y + wl1*l1.y);
        f.z = (w00*a.z + w01*b.z + w10*c2.z + w11*d2.z) * (wl0*l0.z + wl1*l1.z);
        f.w = (w00*a.w + w01*b.w + w10*c2.w + w11*d2.w) * (wl0*l0.w + wl1*l1.w);

        F4[s * F_ROW4 + i * 16 + l16] = f;
    }
    __syncthreads();

    // ---- phase 2: projection ----
    if (tid < SPB) {
        const int s = tid;
        float acc[APP_DIM + 1];
#pragma unroll
        for (int d = 0; d < APP_DIM + 1; d++) acc[d] = 0.f;
        float sigma = 0.f;

        for (int i = 0; i < 3; i++) {
            const int fb = s * F_ROW4 + i * 16;
            const float* wb = Wsm + i * NC_A * 28;

#pragma unroll 2
            for (int c4 = 0; c4 < NC_A / 4; c4++) {
                float4 f = F4[fb + c4];
                const float* r0 = wb + c4 * 4 * 28;
                const float* r1 = r0 + 28;
                const float* r2 = r0 + 56;
                const float* r3 = r0 + 84;
#pragma unroll
                for (int d4 = 0; d4 < 7; d4++) {
                    float4 q0 = *(const float4*)(r0 + d4 * 4);
                    float4 q1 = *(const float4*)(r1 + d4 * 4);
                    float4 q2 = *(const float4*)(r2 + d4 * 4);
                    float4 q3 = *(const float4*)(r3 + d4 * 4);
                    acc[d4*4+0] += f.x*q0.x + f.y*q1.x + f.z*q2.x + f.w*q3.x;
                    acc[d4*4+1] += f.x*q0.y + f.y*q1.y + f.z*q2.y + f.w*q3.y;
                    acc[d4*4+2] += f.x*q0.z + f.y*q1.z + f.z*q2.z + f.w*q3.z;
                    acc[d4*4+3] += f.x*q0.w + f.y*q1.w + f.z*q2.w + f.w*q3.w;
                }
            }
#pragma unroll
            for (int c4 = NC_A / 4; c4 < NCH / 4; c4++) {
                float4 f = F4[fb + c4];
                sigma += f.x + f.y + f.z + f.w;
            }
        }

        long n = base + s;
        if (n < N) {
            out[n] = sigma;
            float* ao = out + N + n * APP_DIM;
#pragma unroll
            for (int d = 0; d < APP_DIM; d++) ao[d] = acc[d];
        }
    }
}

extern "C" void kernel_launch(void* const* d_in, const int* in_sizes, int n_in,
                              void* d_out, int out_size) {
    const float* xyz   = (const float*)d_in[0];   // (N, 3)
    const float* plane = (const float*)d_in[1];   // (3, 64, 300, 300)
    const float* line  = (const float*)d_in[2];   // (3, 64, 300, 1)
    const float* W     = (const float*)d_in[3];   // (27, 144)
    float* out = (float*)d_out;
    int N = in_sizes[0] / 3;

    transpose_plane_kernel<<<dim3(3 * RES, 10), 256>>>(plane);
    transpose_line_kernel<<<3 * RES, NCH>>>(line);

    int smem_bytes = SMEM_FLOATS * (int)sizeof(float);   // 111648
    cudaFuncSetAttribute(fused_kernel,
                         cudaFuncAttributeMaxDynamicSharedMemorySize, smem_bytes);
    int grid = (N + SPB - 1) / SPB;
    fused_kernel<<<grid, 128, smem_bytes>>>(xyz, W, out, N);
}

// round 3
// speedup vs baseline: 1.3450x; 1.0585x over previous
#include <cuda_runtime.h>

#define RES 300
#define NCH 64            // NC_A + NC_D
#define NC_A 48
#define APP_DIM 27
#define SPB 120           // samples per block

// Scratch (zero-initialized device globals; pads never written -> stay 0)
__device__ float g_plane_t[3 * RES * RES * NCH + 64];  // (i, h, w, c) + pad
__device__ float g_line_t[3 * RES * NCH + 64];         // (i, h, c)    + pad

// ---------------------------------------------------------------------------
// Merged transpose: plane (3,64,300,300)->(3,300,300,64), line -> (3,300,64)
// grid (900, 11): y in [0,10) = plane chunks, y == 10 = line column
// ---------------------------------------------------------------------------
__global__ void transpose_kernel(const float* __restrict__ plane,
                                 const float* __restrict__ line) {
    int ih = blockIdx.x;            // 0..899
    int i = ih / RES, h = ih % RES;

    if (blockIdx.y == 10) {
        if (threadIdx.x < NCH)
            g_line_t[((size_t)i * RES + h) * NCH + threadIdx.x] =
                line[((size_t)i * NCH + threadIdx.x) * RES + h];
        return;
    }

    int w0 = blockIdx.y * 30;
    __shared__ float tile[NCH][31];

    for (int idx = threadIdx.x; idx < NCH * 30; idx += blockDim.x) {
        int c = idx / 30, w = idx % 30;
        tile[c][w] = plane[(((size_t)i * NCH + c) * RES + h) * RES + w0 + w];
    }
    __syncthreads();
    float* dst = g_plane_t + (((size_t)i * RES + h) * RES + w0) * NCH;
    for (int idx = threadIdx.x; idx < NCH * 30; idx += blockDim.x) {
        int w = idx / NCH, c = idx % NCH;
        dst[(size_t)w * NCH + c] = tile[c][w];
    }
}

// ---------------------------------------------------------------------------
// Fused kernel:
//   phase 1: one WARP per sample; per mode 3 fully-coalesced 512B loads
//            (both x/z halves at once), shfl_xor(16) blends the halves
//   phase 2: one thread per sample: 144x28 projection from smem
// smem (floats): xyz[360] | Wsm[144][28] | Fsm[SPB][196]
// ---------------------------------------------------------------------------
#define XYZ_OFF 0
#define W_OFF   (3 * SPB)                       // 360
#define F_OFF   (W_OFF + 144 * 28)              // 4392
#define SMEM_FLOATS (F_OFF + SPB * 196)         // 27912 -> 111648 bytes
#define F_ROW4  49                              // 196/4 float4 per row

__global__ void __launch_bounds__(128, 2)
fused_kernel(const float* __restrict__ xyz,
             const float* __restrict__ basisW,   // (27, 144) row-major
             float* __restrict__ out, int N)
{
    extern __shared__ __align__(16) float sm[];
    float*  xyzsm = sm + XYZ_OFF;
    float*  Wsm   = sm + W_OFF;
    float4* F4    = (float4*)(sm + F_OFF);

    const int tid = threadIdx.x;
    const long base = (long)blockIdx.x * SPB;

    // ---- phase 0: stage xyz + W ----
    for (int idx = tid; idx < 3 * SPB; idx += 128) {
        long g = base * 3 + idx;
        xyzsm[idx] = (g < (long)3 * N) ? xyz[g] : 0.f;
    }
    for (int idx = tid; idx < APP_DIM * 144; idx += 128) {
        int d = idx / 144, j = idx - d * 144;
        Wsm[j * 28 + d] = basisW[idx];
    }
    if (tid < 144) Wsm[tid * 28 + 27] = 0.f;
    __syncthreads();

    // ---- phase 1: warp-per-sample gather/blend ----
    const float4* GP = (const float4*)g_plane_t;
    const float4* GL = (const float4*)g_line_t;
    const int lane = tid & 31;
    const int wrp  = tid >> 5;          // 0..3
    const int xh   = lane >> 4;         // 0/1: x (and z) half
    const int c4   = lane & 15;         // channel quad

#pragma unroll 2
    for (int s = wrp; s < SPB; s += 4) {
        float cx = xyzsm[s * 3 + 0];
        float cy = xyzsm[s * 3 + 1];
        float cz = xyzsm[s * 3 + 2];

        float4 av[3], bv[3], lv[3];
        float  wxv[3], wyv[3], wzv[3];

#pragma unroll
        for (int i = 0; i < 3; i++) {
            // MAT_MODE = {0,1},{0,2},{1,2}; VEC_MODE = {2,1,0}
            float gx = (i == 2) ? cy : cx;
            float gy = (i == 0) ? cy : cz;
            float gz = (i == 0) ? cz : ((i == 1) ? cy : cx);

            float ix = (gx + 1.f) * 0.5f * (float)(RES - 1);
            float iy = (gy + 1.f) * 0.5f * (float)(RES - 1);
            float iz = (gz + 1.f) * 0.5f * (float)(RES - 1);
            float x0f = floorf(ix), y0f = floorf(iy), z0f = floorf(iz);
            int x0 = (int)x0f, y0 = (int)y0f, z0 = (int)z0f;
            float wx = ix - x0f, wy = iy - y0f, wz = iz - z0f;
            int y1 = y0 + 1;
            if (y1 > RES - 1) { y1 = RES - 1; wy = 0.f; }
            // x/z edges: lane xh=1 reads one texel past (zero pad), weight 0
            if (x0 + 1 > RES - 1) wx = 0.f;
            if (z0 + 1 > RES - 1) wz = 0.f;
            wxv[i] = wx; wyv[i] = wy; wzv[i] = wz;

            int rx = (i * RES + y0) * RES + x0 + xh;
            int ry = (i * RES + y1) * RES + x0 + xh;
            int rz =  i * RES + z0 + xh;
            av[i] = GP[rx * 16 + c4];        // y0 row, both x halves
            bv[i] = GP[ry * 16 + c4];        // y1 row
            lv[i] = GL[rz * 16 + c4];        // line, both z halves
        }

#pragma unroll
        for (int i = 0; i < 3; i++) {
            float hx = xh ? wxv[i] : 1.f - wxv[i];
            float hz = xh ? wzv[i] : 1.f - wzv[i];
            float wy1 = wyv[i], wy0 = 1.f - wy1;

            float4 t, u;
            t.x = hx * (av[i].x * wy0 + bv[i].x * wy1);
            t.y = hx * (av[i].y * wy0 + bv[i].y * wy1);
            t.z = hx * (av[i].z * wy0 + bv[i].z * wy1);
            t.w = hx * (av[i].w * wy0 + bv[i].w * wy1);
            u.x = hz * lv[i].x;
            u.y = hz * lv[i].y;
            u.z = hz * lv[i].z;
            u.w = hz * lv[i].w;

            t.x += __shfl_xor_sync(0xffffffffu, t.x, 16);
            t.y += __shfl_xor_sync(0xffffffffu, t.y, 16);
            t.z += __shfl_xor_sync(0xffffffffu, t.z, 16);
            t.w += __shfl_xor_sync(0xffffffffu, t.w, 16);
            u.x += __shfl_xor_sync(0xffffffffu, u.x, 16);
            u.y += __shfl_xor_sync(0xffffffffu, u.y, 16);
            u.z += __shfl_xor_sync(0xffffffffu, u.z, 16);
            u.w += __shfl_xor_sync(0xffffffffu, u.w, 16);

            if (xh == 0) {
                float4 f;
                f.x = t.x * u.x; f.y = t.y * u.y;
                f.z = t.z * u.z; f.w = t.w * u.w;
                F4[s * F_ROW4 + i * 16 + c4] = f;
            }
        }
    }
    __syncthreads();

    // ---- phase 2: projection ----
    if (tid < SPB) {
        const int s = tid;
        float acc[APP_DIM + 1];
#pragma unroll
        for (int d = 0; d < APP_DIM + 1; d++) acc[d] = 0.f;
        float sigma = 0.f;

        for (int i = 0; i < 3; i++) {
            const int fb = s * F_ROW4 + i * 16;
            const float* wb = Wsm + i * NC_A * 28;

#pragma unroll 2
            for (int c4i = 0; c4i < NC_A / 4; c4i++) {
                float4 f = F4[fb + c4i];
                const float* r0 = wb + c4i * 4 * 28;
                const float* r1 = r0 + 28;
                const float* r2 = r0 + 56;
                const float* r3 = r0 + 84;
#pragma unroll
                for (int d4 = 0; d4 < 7; d4++) {
                    float4 q0 = *(const float4*)(r0 + d4 * 4);
                    float4 q1 = *(const float4*)(r1 + d4 * 4);
                    float4 q2 = *(const float4*)(r2 + d4 * 4);
                    float4 q3 = *(const float4*)(r3 + d4 * 4);
                    acc[d4*4+0] += f.x*q0.x + f.y*q1.x + f.z*q2.x + f.w*q3.x;
                    acc[d4*4+1] += f.x*q0.y + f.y*q1.y + f.z*q2.y + f.w*q3.y;
                    acc[d4*4+2] += f.x*q0.z + f.y*q1.z + f.z*q2.z + f.w*q3.z;
                    acc[d4*4+3] += f.x*q0.w + f.y*q1.w + f.z*q2.w + f.w*q3.w;
                }
            }
#pragma unroll
            for (int c4i = NC_A / 4; c4i < NCH / 4; c4i++) {
                float4 f = F4[fb + c4i];
                sigma += f.x + f.y + f.z + f.w;
            }
        }

        long n = base + s;
        if (n < N) {
            out[n] = sigma;
            float* ao = out + N + n * APP_DIM;
#pragma unroll
            for (int d = 0; d < APP_DIM; d++) ao[d] = acc[d];
        }
    }
}

extern "C" void kernel_launch(void* const* d_in, const int* in_sizes, int n_in,
                              void* d_out, int out_size) {
    const float* xyz   = (const float*)d_in[0];   // (N, 3)
    const float* plane = (const float*)d_in[1];   // (3, 64, 300, 300)
    const float* line  = (const float*)d_in[2];   // (3, 64, 300, 1)
    const float* W     = (const float*)d_in[3];   // (27, 144)
    float* out = (float*)d_out;
    int N = in_sizes[0] / 3;

    transpose_kernel<<<dim3(3 * RES, 11), 256>>>(plane, line);

    int smem_bytes = SMEM_FLOATS * (int)sizeof(float);   // 111648
    cudaFuncSetAttribute(fused_kernel,
                         cudaFuncAttributeMaxDynamicSharedMemorySize, smem_bytes);
    int grid = (N + SPB - 1) / SPB;
    fused_kernel<<<grid, 128, smem_bytes>>>(xyz, W, out, N);
}